// round 15
// baseline (speedup 1.0000x reference)
#include <cuda_runtime.h>
#include <cuda_bf16.h>
#include <cstdint>

#define N_NODES 10000
#define N_EDGES 640000
#define D 128
#define CAP 160            // padded CSR bucket capacity (mean deg 64, sigma 8)
#define GEMM_BLOCKS 79     // ceil(10000/128)
#define NBLK 148
#define NTHR 1024
#define NWARP (NBLK * 32)  // 4736
#define FILL_END 96        // blocks [0,96): CSR fill
#define CVT_END 147        // blocks [96,147): bf16 cvt ; block 147: wc fold

// ---------------- scratch (device globals; no allocation allowed) ----------
__device__ float g_agg[N_NODES * D];
__device__ uint2 g_xh[N_NODES * 32];  // x in packed bf16
__device__ float4 g_vself[N_NODES];   // (A1 , A3) self terms
__device__ float4 g_vnb[N_NODES];     // (A2 , A4) neighbor terms
__device__ float2 g_ps[N_NODES];
__device__ float2 g_pd[N_NODES];
__device__ float g_wc[D * 8];         // [A1|A2|A3|A4] rows
__device__ float g_c[4];
__device__ int g_cnt[N_NODES];        // zeroed in k_tailedge (replay invariant)
__device__ int g_csr[N_NODES * CAP];
__device__ unsigned g_bar_a[2];       // self-resetting barriers
__device__ unsigned g_bar_d[2];

// ---------------- helpers ---------------------------------------------------
__device__ __forceinline__ uint32_t f2tf32(float v) {
    uint32_t t;
    asm("cvt.rna.tf32.f32 %0, %1;" : "=r"(t) : "f"(v));
    return t;
}
__device__ __forceinline__ void mma_tf32(float* c, const uint32_t* a,
                                         uint32_t b0, uint32_t b1) {
    asm volatile(
        "mma.sync.aligned.m16n8k8.row.col.f32.tf32.tf32.f32 "
        "{%0,%1,%2,%3}, {%4,%5,%6,%7}, {%8,%9}, {%0,%1,%2,%3};"
        : "+f"(c[0]), "+f"(c[1]), "+f"(c[2]), "+f"(c[3])
        : "r"(a[0]), "r"(a[1]), "r"(a[2]), "r"(a[3]), "r"(b0), "r"(b1));
}

// grid barrier: all NBLK CTAs co-resident (148 blocks, 1 per SM, wave 1)
__device__ __forceinline__ void grid_sync(int i) {
    __syncthreads();
    if (threadIdx.x == 0) {
        __threadfence();
        unsigned a = atomicAdd(&g_bar_a[i], 1u) + 1u;
        if (a < NBLK) {
            while (*(volatile unsigned*)&g_bar_a[i] < NBLK) {}
        }
        __threadfence();
        unsigned dcnt = atomicAdd(&g_bar_d[i], 1u) + 1u;
        if (dcnt == NBLK) {
            g_bar_a[i] = 0u;
            __threadfence();
            g_bar_d[i] = 0u;
        }
    }
    __syncthreads();
}

__device__ __forceinline__ void acc_u2(uint2 u, float& x, float& y, float& z,
                                       float& w) {
    float2 f;
    f = __bfloat1622float2(*reinterpret_cast<__nv_bfloat162*>(&u.x));
    x += f.x; y += f.y;
    f = __bfloat1622float2(*reinterpret_cast<__nv_bfloat162*>(&u.y));
    z += f.x; w += f.y;
}

// ======== kernel 1: prep (fill | cvt | wc) -> barrier -> pair agg ==========
__global__ void __launch_bounds__(NTHR, 1)
k_prepagg(const int* __restrict__ src, const int* __restrict__ dst,
          const float* __restrict__ x,
          const float* __restrict__ Ws2, const float* __restrict__ Wn2,
          const float* __restrict__ b2, const float* __restrict__ Wp) {
    __shared__ float sWp[256 * 2];
    int bid = blockIdx.x;
    int tid = threadIdx.x;
    int widx = tid >> 5;
    int lane = tid & 31;
    int gw = bid * 32 + widx;

    // ---- phase A: specialized block ranges --------------------------------
    if (bid < FILL_END) {
        // CSR fill: 96*1024 = 98304 threads over 80000 8-edge groups
        int tg = bid * NTHR + tid;
        for (int t = tg; t < N_EDGES / 8; t += FILL_END * NTHR) {
            int4 s0 = ((const int4*)src)[2 * t];
            int4 s1 = ((const int4*)src)[2 * t + 1];
            int4 d0 = ((const int4*)dst)[2 * t];
            int4 d1 = ((const int4*)dst)[2 * t + 1];
            int p0 = atomicAdd(&g_cnt[d0.x], 1);
            int p1 = atomicAdd(&g_cnt[d0.y], 1);
            int p2 = atomicAdd(&g_cnt[d0.z], 1);
            int p3 = atomicAdd(&g_cnt[d0.w], 1);
            int p4 = atomicAdd(&g_cnt[d1.x], 1);
            int p5 = atomicAdd(&g_cnt[d1.y], 1);
            int p6 = atomicAdd(&g_cnt[d1.z], 1);
            int p7 = atomicAdd(&g_cnt[d1.w], 1);
            if (p0 < CAP) g_csr[d0.x * CAP + p0] = s0.x;
            if (p1 < CAP) g_csr[d0.y * CAP + p1] = s0.y;
            if (p2 < CAP) g_csr[d0.z * CAP + p2] = s0.z;
            if (p3 < CAP) g_csr[d0.w * CAP + p3] = s0.w;
            if (p4 < CAP) g_csr[d1.x * CAP + p4] = s1.x;
            if (p5 < CAP) g_csr[d1.y * CAP + p5] = s1.y;
            if (p6 < CAP) g_csr[d1.z * CAP + p6] = s1.z;
            if (p7 < CAP) g_csr[d1.w * CAP + p7] = s1.w;
        }
    } else if (bid < CVT_END) {
        // bf16 cvt: 51 blocks over 160000 uint4 items (~3 each)
        int tg = (bid - FILL_END) * NTHR + tid;
        for (int i = tg; i < N_NODES * 16; i += (CVT_END - FILL_END) * NTHR) {
            float4 a = ((const float4*)x)[2 * i];
            float4 b = ((const float4*)x)[2 * i + 1];
            __nv_bfloat162 q0 = __floats2bfloat162_rn(a.x, a.y);
            __nv_bfloat162 q1 = __floats2bfloat162_rn(a.z, a.w);
            __nv_bfloat162 q2 = __floats2bfloat162_rn(b.x, b.y);
            __nv_bfloat162 q3 = __floats2bfloat162_rn(b.z, b.w);
            uint4 u;
            u.x = *reinterpret_cast<unsigned*>(&q0);
            u.y = *reinterpret_cast<unsigned*>(&q1);
            u.z = *reinterpret_cast<unsigned*>(&q2);
            u.w = *reinterpret_cast<unsigned*>(&q3);
            ((uint4*)g_xh)[i] = u;
        }
    } else {
        for (int i = tid; i < 512; i += NTHR) sWp[i] = Wp[i];
        __syncthreads();
        if (tid < 128) {
            int t = tid;
            float a[8] = {0, 0, 0, 0, 0, 0, 0, 0};
#pragma unroll 4
            for (int j = 0; j < D; j++) {
                float ws = Ws2[t * D + j];
                float wn = Wn2[t * D + j];
                float p0 = sWp[j * 2], p1 = sWp[j * 2 + 1];
                float q0 = sWp[(128 + j) * 2], q1 = sWp[(128 + j) * 2 + 1];
                a[0] += ws * p0; a[1] += ws * p1;
                a[2] += wn * p0; a[3] += wn * p1;
                a[4] += ws * q0; a[5] += ws * q1;
                a[6] += wn * q0; a[7] += wn * q1;
            }
#pragma unroll
            for (int j = 0; j < 8; j++) g_wc[t * 8 + j] = a[j];
        }
        if (tid < 4) {
            int half = tid >> 1, c = tid & 1;
            float s = 0.f;
            for (int j = 0; j < D; j++)
                s += b2[j] * sWp[(half * 128 + j) * 2 + c];
            g_c[tid] = s;
        }
    }
    grid_sync(0);
    cudaTriggerProgrammaticLaunchCompletion();  // release k_layer_mma

    // ---- phase B: PAIR-interleaved mean aggregation (2 nodes per warp) ----
    for (int p = gw; p * 2 < N_NODES; p += NWARP) {
        int na = 2 * p, nbn = 2 * p + 1;   // N_NODES even -> both valid
        int da = g_cnt[na], db = g_cnt[nbn];
        int bega = na * CAP, begb = nbn * CAP;
        float ax = 0.f, ay = 0.f, az = 0.f, aw = 0.f;
        float bx = 0.f, by = 0.f, bz = 0.f, bw = 0.f;
        int dmax = max(da, db);
        for (int base = 0; base < dmax; base += 32) {
            int mya = (base + lane < da) ? g_csr[bega + base + lane] : 0;
            int myb = (base + lane < db) ? g_csr[begb + base + lane] : 0;
            int cnta = min(32, da - base);   // may be <= 0
            int cntb = min(32, db - base);
            for (int j = 0; j < 32; j += 8) {
                int va = cnta - j;           // valid count this round (a)
                int vb = cntb - j;
                if (va <= 0 && vb <= 0) break;
                uint2 ua[8], ub[8];
#pragma unroll
                for (int q = 0; q < 8; q++) {
                    if (q < va) {
                        int s = __shfl_sync(0xffffffffu, mya, j + q);
                        ua[q] = g_xh[s * 32 + lane];
                    }
                    if (q < vb) {
                        int s = __shfl_sync(0xffffffffu, myb, j + q);
                        ub[q] = g_xh[s * 32 + lane];
                    }
                }
#pragma unroll
                for (int q = 0; q < 8; q++) {
                    if (q < va) acc_u2(ua[q], ax, ay, az, aw);
                    if (q < vb) acc_u2(ub[q], bx, by, bz, bw);
                }
            }
        }
        float inva = 1.0f / (float)(da < 1 ? 1 : da);
        float invb = 1.0f / (float)(db < 1 ? 1 : db);
        float4 ra, rb;
        ra.x = ax * inva; ra.y = ay * inva; ra.z = az * inva; ra.w = aw * inva;
        rb.x = bx * invb; rb.y = by * invb; rb.z = bz * invb; rb.w = bw * invb;
        *(float4*)(g_agg + (size_t)na * D + lane * 4) = ra;
        *(float4*)(g_agg + (size_t)nbn * D + lane * 4) = rb;
    }
}

// ======== kernel 2: mma.sync tf32 layer 1 + fused projection ================
#define ASTR 132   // 128 + 4 pad (u32 units)

__global__ void __launch_bounds__(256, 1)
k_layer_mma(const float* __restrict__ x, const float* __restrict__ agg,
            const float* __restrict__ Wself, const float* __restrict__ Wneigh,
            const float* __restrict__ bias) {
    cudaTriggerProgrammaticLaunchCompletion();  // release k_tailedge early

    extern __shared__ uint32_t smu[];
    uint32_t* sA = smu;
    uint32_t* sB = smu + 128 * ASTR;
    float* sWc = (float*)(smu + 2 * 128 * ASTR);
    float* sBias = sWc + 1024;

    int tid = threadIdx.x;
    int wid = tid >> 5;
    int lane = tid & 31;
    int nb = blockIdx.x * 128;
    int valid = min(128, N_NODES - nb);

    // prologue: x, Wself, bias, wc — complete when the trigger fired
    for (int it = tid; it < 128 * 32; it += 256) {
        int r = it >> 5, q = it & 31;
        float4 vx = make_float4(0.f, 0.f, 0.f, 0.f);
        if (r < valid) vx = ((const float4*)x)[(size_t)(nb + r) * 32 + q];
        uint32_t* a = sA + r * ASTR + q * 4;
        a[0] = f2tf32(vx.x); a[1] = f2tf32(vx.y);
        a[2] = f2tf32(vx.z); a[3] = f2tf32(vx.w);
        float4 w = ((const float4*)Wself)[it];
        uint32_t* bp = sB + r * ASTR + q * 4;
        bp[0] = f2tf32(w.x); bp[1] = f2tf32(w.y);
        bp[2] = f2tf32(w.z); bp[3] = f2tf32(w.w);
    }
    for (int i = tid; i < D * 2; i += 256)
        ((float4*)sWc)[i] = ((const float4*)g_wc)[i];
    if (tid < 32) ((float4*)sBias)[tid] = ((const float4*)bias)[tid];
    __syncthreads();

    int wm = wid & 3, wn = wid >> 2;
    int tg8 = lane >> 2, tq = lane & 3;

    float c[2][8][4];
#pragma unroll
    for (int mi = 0; mi < 2; mi++)
#pragma unroll
        for (int ni = 0; ni < 8; ni++)
#pragma unroll
            for (int k = 0; k < 4; k++) c[mi][ni][k] = 0.f;

    // ---- pass 0: C = X @ Ws (overlaps agg phase of k_prepagg) ----
#pragma unroll 2
    for (int kc = 0; kc < 16; kc++) {
        int k0 = kc * 8;
        uint32_t a[2][4];
#pragma unroll
        for (int mi = 0; mi < 2; mi++) {
            int row = 32 * wm + 16 * mi + tg8;
            a[mi][0] = sA[row * ASTR + k0 + tq];
            a[mi][1] = sA[(row + 8) * ASTR + k0 + tq];
            a[mi][2] = sA[row * ASTR + k0 + tq + 4];
            a[mi][3] = sA[(row + 8) * ASTR + k0 + tq + 4];
        }
#pragma unroll
        for (int ni = 0; ni < 8; ni++) {
            int col = 64 * wn + 8 * ni + tg8;
            uint32_t b0 = sB[(k0 + tq) * ASTR + col];
            uint32_t b1r = sB[(k0 + tq + 4) * ASTR + col];
            mma_tf32(c[0][ni], a[0], b0, b1r);
            mma_tf32(c[1][ni], a[1], b0, b1r);
        }
    }
    __syncthreads();

    cudaGridDependencySynchronize();   // wait for k_prepagg (g_agg complete)

    // ---- load pass 1 tiles: A = agg rows, B = Wneigh ----
    for (int it = tid; it < 128 * 32; it += 256) {
        int r = it >> 5, q = it & 31;
        float4 vm = make_float4(0.f, 0.f, 0.f, 0.f);
        if (r < valid)
            vm = ((const float4*)agg)[(size_t)(nb + r) * 32 + q];
        uint32_t* a = sA + r * ASTR + q * 4;
        a[0] = f2tf32(vm.x); a[1] = f2tf32(vm.y);
        a[2] = f2tf32(vm.z); a[3] = f2tf32(vm.w);
        float4 w = ((const float4*)Wneigh)[it];
        uint32_t* bp = sB + r * ASTR + q * 4;
        bp[0] = f2tf32(w.x); bp[1] = f2tf32(w.y);
        bp[2] = f2tf32(w.z); bp[3] = f2tf32(w.w);
    }
    __syncthreads();

    // ---- pass 1: C += M @ Wn ----
#pragma unroll 2
    for (int kc = 0; kc < 16; kc++) {
        int k0 = kc * 8;
        uint32_t a[2][4];
#pragma unroll
        for (int mi = 0; mi < 2; mi++) {
            int row = 32 * wm + 16 * mi + tg8;
            a[mi][0] = sA[row * ASTR + k0 + tq];
            a[mi][1] = sA[(row + 8) * ASTR + k0 + tq];
            a[mi][2] = sA[row * ASTR + k0 + tq + 4];
            a[mi][3] = sA[(row + 8) * ASTR + k0 + tq + 4];
        }
#pragma unroll
        for (int ni = 0; ni < 8; ni++) {
            int col = 64 * wn + 8 * ni + tg8;
            uint32_t b0 = sB[(k0 + tq) * ASTR + col];
            uint32_t b1r = sB[(k0 + tq + 4) * ASTR + col];
            mma_tf32(c[0][ni], a[0], b0, b1r);
            mma_tf32(c[1][ni], a[1], b0, b1r);
        }
    }

    __syncthreads();
    float* sH = (float*)sA;
#pragma unroll
    for (int mi = 0; mi < 2; mi++) {
        int r0 = 32 * wm + 16 * mi + tg8;
#pragma unroll
        for (int ni = 0; ni < 8; ni++) {
            int cb = 64 * wn + 8 * ni + 2 * tq;
            sH[r0 * ASTR + cb] = fmaxf(c[mi][ni][0] + sBias[cb], 0.f);
            sH[r0 * ASTR + cb + 1] = fmaxf(c[mi][ni][1] + sBias[cb + 1], 0.f);
            sH[(r0 + 8) * ASTR + cb] = fmaxf(c[mi][ni][2] + sBias[cb], 0.f);
            sH[(r0 + 8) * ASTR + cb + 1] =
                fmaxf(c[mi][ni][3] + sBias[cb + 1], 0.f);
        }
    }
    __syncthreads();

    int node = tid >> 1;
    int half = tid & 1;
    float pv[8] = {0, 0, 0, 0, 0, 0, 0, 0};
    const float* hrow = sH + node * ASTR + half * 64;
#pragma unroll 8
    for (int j = 0; j < 64; j++) {
        float h = hrow[j];
        int col = half * 64 + j;
        float4 w0 = *(const float4*)(sWc + col * 8);
        float4 w1 = *(const float4*)(sWc + col * 8 + 4);
        pv[0] += h * w0.x; pv[1] += h * w0.y;
        pv[2] += h * w0.z; pv[3] += h * w0.w;
        pv[4] += h * w1.x; pv[5] += h * w1.y;
        pv[6] += h * w1.z; pv[7] += h * w1.w;
    }
#pragma unroll
    for (int m = 0; m < 8; m++)
        pv[m] += __shfl_xor_sync(0xffffffffu, pv[m], 1);
    int gn = nb + node;
    if (half == 0 && gn < N_NODES) {
        g_vself[gn] = make_float4(pv[0], pv[1], pv[4], pv[5]);
        g_vnb[gn] = make_float4(pv[2], pv[3], pv[6], pv[7]);
    }
}

// ======== kernel 3: tiny aggregation -> barrier -> edge scores ==============
__global__ void __launch_bounds__(NTHR, 1)
k_tailedge(const int* __restrict__ src, const int* __restrict__ dst,
           const float* __restrict__ bpred, float* __restrict__ out) {
    int bid = blockIdx.x;
    int tid = threadIdx.x;
    int lane = tid & 31;
    int gw = bid * 32 + (tid >> 5);
    int gid = bid * NTHR + tid;

    // preload for agg2 phase (8 lanes/node, 4 nodes/warp; single pass)
    int sub = lane & 7;
    int n = gw * 4 + (lane >> 3);          // 0..18943
    int d = 0, beg = 0;
    if (n < N_NODES) {
        d = g_cnt[n];
        beg = n * CAP;
    }
    int idx[8];
#pragma unroll
    for (int i = 0; i < 8; i++)
        idx[i] = (sub + 8 * i < d) ? g_csr[beg + sub + 8 * i] : -1;

    // preload for edge phase (one 8-edge group per thread)
    int4 es0 = make_int4(0, 0, 0, 0), es1 = es0, ed0 = es0, ed1 = es0;
    bool has_edge = gid < N_EDGES / 8;
    if (has_edge) {
        es0 = ((const int4*)src)[2 * gid];
        es1 = ((const int4*)src)[2 * gid + 1];
        ed0 = ((const int4*)dst)[2 * gid];
        ed1 = ((const int4*)dst)[2 * gid + 1];
    }
    float b0 = __ldg(bpred) + g_c[0] + g_c[2];
    float b1v = __ldg(bpred + 1) + g_c[1] + g_c[3];

    cudaGridDependencySynchronize();   // wait k_layer_mma (g_vnb/g_vself)

    // ---- agg2: gather projected neighbor terms, reduce over 8 lanes -------
    {
        float ax = 0.f, ay = 0.f, az = 0.f, aw = 0.f;
#pragma unroll
        for (int i = 0; i < 8; i++) {
            if (idx[i] >= 0) {
                float4 v = g_vnb[idx[i]];
                ax += v.x; ay += v.y; az += v.z; aw += v.w;
            }
        }
        for (int i = 64 + sub; i < d; i += 8) {   // rare tail (deg > 64)
            int s = g_csr[beg + i];
            float4 v = g_vnb[s];
            ax += v.x; ay += v.y; az += v.z; aw += v.w;
        }
#pragma unroll
        for (int off = 4; off > 0; off >>= 1) {
            ax += __shfl_xor_sync(0xffffffffu, ax, off);
            ay += __shfl_xor_sync(0xffffffffu, ay, off);
            az += __shfl_xor_sync(0xffffffffu, az, off);
            aw += __shfl_xor_sync(0xffffffffu, aw, off);
        }
        if (sub == 0 && n < N_NODES) {
            float inv = 1.0f / (float)(d < 1 ? 1 : d);
            float4 vs = g_vself[n];
            g_ps[n] = make_float2(vs.x + ax * inv, vs.y + ay * inv);
            g_pd[n] = make_float2(vs.z + az * inv, vs.w + aw * inv);
            g_cnt[n] = 0;   // restore invariant for next graph replay
        }
    }

    grid_sync(1);

    // ---- edge scores -------------------------------------------------------
    if (has_edge) {
        int t = gid;
        float2 a0 = g_ps[es0.x], a1 = g_ps[es0.y];
        float2 a2 = g_ps[es0.z], a3 = g_ps[es0.w];
        float2 a4 = g_ps[es1.x], a5 = g_ps[es1.y];
        float2 a6 = g_ps[es1.z], a7 = g_ps[es1.w];
        float2 c0 = g_pd[ed0.x], c1 = g_pd[ed0.y];
        float2 c2 = g_pd[ed0.z], c3 = g_pd[ed0.w];
        float2 c4 = g_pd[ed1.x], c5 = g_pd[ed1.y];
        float2 c6 = g_pd[ed1.z], c7 = g_pd[ed1.w];
        float4 o;
        o = make_float4(a0.x + c0.x + b0, a0.y + c0.y + b1v,
                        a1.x + c1.x + b0, a1.y + c1.y + b1v);
        ((float4*)out)[t * 4] = o;
        o = make_float4(a2.x + c2.x + b0, a2.y + c2.y + b1v,
                        a3.x + c3.x + b0, a3.y + c3.y + b1v);
        ((float4*)out)[t * 4 + 1] = o;
        o = make_float4(a4.x + c4.x + b0, a4.y + c4.y + b1v,
                        a5.x + c5.x + b0, a5.y + c5.y + b1v);
        ((float4*)out)[t * 4 + 2] = o;
        o = make_float4(a6.x + c6.x + b0, a6.y + c6.y + b1v,
                        a7.x + c7.x + b0, a7.y + c7.y + b1v);
        ((float4*)out)[t * 4 + 3] = o;
    }
}

// ---------------- launcher (3 kernels, PDL-chained) -------------------------
static void launch_pdl(const void* func, dim3 grid, dim3 block, size_t smem,
                       void** args) {
    cudaLaunchConfig_t cfg = {};
    cfg.gridDim = grid;
    cfg.blockDim = block;
    cfg.dynamicSmemBytes = smem;
    cfg.stream = 0;
    cudaLaunchAttribute attr;
    attr.id = cudaLaunchAttributeProgrammaticStreamSerialization;
    attr.val.programmaticStreamSerializationAllowed = 1;
    cfg.attrs = &attr;
    cfg.numAttrs = 1;
    cudaLaunchKernelExC(&cfg, func, args);
}

extern "C" void kernel_launch(void* const* d_in, const int* in_sizes, int n_in,
                              void* d_out, int out_size) {
    const float* x = (const float*)d_in[0];
    const int* src = (const int*)d_in[1];
    const int* dst = (const int*)d_in[2];
    const float* Wself1 = (const float*)d_in[3];
    const float* Wneigh1 = (const float*)d_in[4];
    const float* b1 = (const float*)d_in[5];
    const float* Wself2 = (const float*)d_in[6];
    const float* Wneigh2 = (const float*)d_in[7];
    const float* b2 = (const float*)d_in[8];
    const float* Wpred = (const float*)d_in[9];
    const float* bpred = (const float*)d_in[10];
    float* out = (float*)d_out;

    size_t layer_smem = (size_t)(2 * 128 * ASTR + 1024 + 128) * 4;
    cudaFuncSetAttribute(k_layer_mma,
                         cudaFuncAttributeMaxDynamicSharedMemorySize,
                         (int)layer_smem);

    float* p_agg;
    cudaGetSymbolAddress((void**)&p_agg, g_agg);

    k_prepagg<<<NBLK, NTHR>>>(src, dst, x, Wself2, Wneigh2, b2, Wpred);
    {
        void* args[] = {(void*)&x, (void*)&p_agg, (void*)&Wself1,
                        (void*)&Wneigh1, (void*)&b1};
        launch_pdl((const void*)k_layer_mma, dim3(GEMM_BLOCKS), dim3(256),
                   layer_smem, args);
    }
    {
        void* args[] = {(void*)&src, (void*)&dst, (void*)&bpred, (void*)&out};
        launch_pdl((const void*)k_tailedge, dim3(NBLK), dim3(NTHR), 0, args);
    }
}

// round 16
// speedup vs baseline: 1.0584x; 1.0584x over previous
#include <cuda_runtime.h>
#include <cuda_bf16.h>
#include <cstdint>

#define N_NODES 10000
#define N_EDGES 640000
#define D 128
#define CAP 160            // padded CSR bucket capacity (mean deg 64, sigma 8)
#define FILL_BLOCKS 313    // ceil(640000/8/256)
#define CVT_BLOCKS 1250    // 10000*32/256
#define GEMM_BLOCKS 79     // ceil(10000/128)
#define NBLK 148
#define NTHR 1024

// ---------------- scratch (device globals; no allocation allowed) ----------
__device__ float g_agg[N_NODES * D];
__device__ uint2 g_xh[N_NODES * 32];  // x in packed bf16
__device__ float4 g_vself[N_NODES];   // (A1 , A3) self terms
__device__ float4 g_vnb[N_NODES];     // (A2 , A4) neighbor terms
__device__ float2 g_ps[N_NODES];
__device__ float2 g_pd[N_NODES];
__device__ float g_wc[D * 8];         // [A1|A2|A3|A4] rows
__device__ float g_c[4];
__device__ int g_cnt[N_NODES];        // zeroed in k_tailedge (replay invariant)
__device__ int g_csr[N_NODES * CAP];
__device__ unsigned g_bar_a;          // self-resetting barrier (tail kernel)
__device__ unsigned g_bar_d;

// ---------------- helpers ---------------------------------------------------
__device__ __forceinline__ uint32_t f2tf32(float v) {
    uint32_t t;
    asm("cvt.rna.tf32.f32 %0, %1;" : "=r"(t) : "f"(v));
    return t;
}
__device__ __forceinline__ void mma_tf32(float* c, const uint32_t* a,
                                         uint32_t b0, uint32_t b1) {
    asm volatile(
        "mma.sync.aligned.m16n8k8.row.col.f32.tf32.tf32.f32 "
        "{%0,%1,%2,%3}, {%4,%5,%6,%7}, {%8,%9}, {%0,%1,%2,%3};"
        : "+f"(c[0]), "+f"(c[1]), "+f"(c[2]), "+f"(c[3])
        : "r"(a[0]), "r"(a[1]), "r"(a[2]), "r"(a[3]), "r"(b0), "r"(b1));
}

// ======== kernel 1: fused prep (fill | cvt | wc), block-specialized =========
__global__ void k_prep(const int* __restrict__ src, const int* __restrict__ dst,
                       const float* __restrict__ x,
                       const float* __restrict__ Ws2,
                       const float* __restrict__ Wn2,
                       const float* __restrict__ b2,
                       const float* __restrict__ Wp) {
    __shared__ float sWp[256 * 2];
    int b = blockIdx.x;
    int tid = threadIdx.x;
    if (b < FILL_BLOCKS) {
        int t = b * 256 + tid;
        if (t * 8 >= N_EDGES) return;
        int4 s0 = ((const int4*)src)[2 * t], s1 = ((const int4*)src)[2 * t + 1];
        int4 d0 = ((const int4*)dst)[2 * t], d1 = ((const int4*)dst)[2 * t + 1];
        int p0 = atomicAdd(&g_cnt[d0.x], 1);
        int p1 = atomicAdd(&g_cnt[d0.y], 1);
        int p2 = atomicAdd(&g_cnt[d0.z], 1);
        int p3 = atomicAdd(&g_cnt[d0.w], 1);
        int p4 = atomicAdd(&g_cnt[d1.x], 1);
        int p5 = atomicAdd(&g_cnt[d1.y], 1);
        int p6 = atomicAdd(&g_cnt[d1.z], 1);
        int p7 = atomicAdd(&g_cnt[d1.w], 1);
        if (p0 < CAP) g_csr[d0.x * CAP + p0] = s0.x;
        if (p1 < CAP) g_csr[d0.y * CAP + p1] = s0.y;
        if (p2 < CAP) g_csr[d0.z * CAP + p2] = s0.z;
        if (p3 < CAP) g_csr[d0.w * CAP + p3] = s0.w;
        if (p4 < CAP) g_csr[d1.x * CAP + p4] = s1.x;
        if (p5 < CAP) g_csr[d1.y * CAP + p5] = s1.y;
        if (p6 < CAP) g_csr[d1.z * CAP + p6] = s1.z;
        if (p7 < CAP) g_csr[d1.w * CAP + p7] = s1.w;
    } else if (b < FILL_BLOCKS + CVT_BLOCKS) {
        int idx = (b - FILL_BLOCKS) * 256 + tid;
        if (idx >= N_NODES * 32) return;
        float4 v = ((const float4*)x)[idx];
        __nv_bfloat162 q0 = __floats2bfloat162_rn(v.x, v.y);
        __nv_bfloat162 q1 = __floats2bfloat162_rn(v.z, v.w);
        uint2 u;
        u.x = *reinterpret_cast<unsigned*>(&q0);
        u.y = *reinterpret_cast<unsigned*>(&q1);
        g_xh[idx] = u;
    } else {
        for (int i = tid; i < 512; i += 256) sWp[i] = Wp[i];
        __syncthreads();
        int t = tid;
        if (t < 128) {
            float a[8] = {0, 0, 0, 0, 0, 0, 0, 0};
#pragma unroll 4
            for (int j = 0; j < D; j++) {
                float ws = Ws2[t * D + j];
                float wn = Wn2[t * D + j];
                float p0 = sWp[j * 2], p1 = sWp[j * 2 + 1];
                float q0 = sWp[(128 + j) * 2], q1 = sWp[(128 + j) * 2 + 1];
                a[0] += ws * p0; a[1] += ws * p1;
                a[2] += wn * p0; a[3] += wn * p1;
                a[4] += ws * q0; a[5] += ws * q1;
                a[6] += wn * q0; a[7] += wn * q1;
            }
#pragma unroll
            for (int j = 0; j < 8; j++) g_wc[t * 8 + j] = a[j];
        }
        if (t < 4) {
            int half = t >> 1, c = t & 1;
            float s = 0.f;
            for (int j = 0; j < D; j++)
                s += b2[j] * sWp[(half * 128 + j) * 2 + c];
            g_c[t] = s;
        }
    }
}

// ======== kernel 2: standalone pull aggregation (1 node per warp) ===========
__global__ void k_agg(const float* __restrict__ unused) {
    cudaGridDependencySynchronize();   // needs g_cnt/g_csr/g_xh from prep
    cudaTriggerProgrammaticLaunchCompletion();  // release k_layer_mma
    int gid = blockIdx.x * blockDim.x + threadIdx.x;
    int n = gid >> 5;
    int lane = gid & 31;
    if (n >= N_NODES) return;
    int beg = n * CAP;
    int d = g_cnt[n];
    float ax = 0.f, ay = 0.f, az = 0.f, aw = 0.f;
    for (int base = 0; base < d; base += 32) {
        int my = -1;
        if (base + lane < d) my = g_csr[beg + base + lane];
        int cnt = min(32, d - base);
        int j = 0;
        for (; j + 8 <= cnt; j += 8) {
            int ss[8];
#pragma unroll
            for (int q = 0; q < 8; q++)
                ss[q] = __shfl_sync(0xffffffffu, my, j + q);
            uint2 u[8];
#pragma unroll
            for (int q = 0; q < 8; q++) u[q] = g_xh[ss[q] * 32 + lane];
#pragma unroll
            for (int q = 0; q < 8; q++) {
                float2 f;
                f = __bfloat1622float2(
                    *reinterpret_cast<__nv_bfloat162*>(&u[q].x));
                ax += f.x; ay += f.y;
                f = __bfloat1622float2(
                    *reinterpret_cast<__nv_bfloat162*>(&u[q].y));
                az += f.x; aw += f.y;
            }
        }
        for (; j < cnt; j++) {
            int s0 = __shfl_sync(0xffffffffu, my, j);
            uint2 u0 = g_xh[s0 * 32 + lane];
            float2 f;
            f = __bfloat1622float2(*reinterpret_cast<__nv_bfloat162*>(&u0.x));
            ax += f.x; ay += f.y;
            f = __bfloat1622float2(*reinterpret_cast<__nv_bfloat162*>(&u0.y));
            az += f.x; aw += f.y;
        }
    }
    float inv = 1.0f / (float)(d < 1 ? 1 : d);
    float4 r;
    r.x = ax * inv; r.y = ay * inv; r.z = az * inv; r.w = aw * inv;
    *(float4*)(g_agg + (size_t)n * D + lane * 4) = r;
}

// ======== kernel 3: mma.sync tf32 layer 1 + fused projection ================
#define ASTR 132   // 128 + 4 pad (u32 units)

__global__ void __launch_bounds__(256, 1)
k_layer_mma(const float* __restrict__ x, const float* __restrict__ agg,
            const float* __restrict__ Wself, const float* __restrict__ Wneigh,
            const float* __restrict__ bias) {
    cudaTriggerProgrammaticLaunchCompletion();  // release k_tailedge early

    extern __shared__ uint32_t smu[];
    uint32_t* sA = smu;
    uint32_t* sB = smu + 128 * ASTR;
    float* sWc = (float*)(smu + 2 * 128 * ASTR);
    float* sBias = sWc + 1024;

    int tid = threadIdx.x;
    int wid = tid >> 5;
    int lane = tid & 31;
    int nb = blockIdx.x * 128;
    int valid = min(128, N_NODES - nb);

    // prologue: x, Wself, bias, wc — complete when agg's trigger fired
    for (int it = tid; it < 128 * 32; it += 256) {
        int r = it >> 5, q = it & 31;
        float4 vx = make_float4(0.f, 0.f, 0.f, 0.f);
        if (r < valid) vx = ((const float4*)x)[(size_t)(nb + r) * 32 + q];
        uint32_t* a = sA + r * ASTR + q * 4;
        a[0] = f2tf32(vx.x); a[1] = f2tf32(vx.y);
        a[2] = f2tf32(vx.z); a[3] = f2tf32(vx.w);
        float4 w = ((const float4*)Wself)[it];
        uint32_t* bp = sB + r * ASTR + q * 4;
        bp[0] = f2tf32(w.x); bp[1] = f2tf32(w.y);
        bp[2] = f2tf32(w.z); bp[3] = f2tf32(w.w);
    }
    for (int i = tid; i < D * 2; i += 256)
        ((float4*)sWc)[i] = ((const float4*)g_wc)[i];
    if (tid < 32) ((float4*)sBias)[tid] = ((const float4*)bias)[tid];
    __syncthreads();

    int wm = wid & 3, wn = wid >> 2;
    int tg8 = lane >> 2, tq = lane & 3;

    float c[2][8][4];
#pragma unroll
    for (int mi = 0; mi < 2; mi++)
#pragma unroll
        for (int ni = 0; ni < 8; ni++)
#pragma unroll
            for (int k = 0; k < 4; k++) c[mi][ni][k] = 0.f;

    // ---- pass 0: C = X @ Ws (overlaps k_agg) ----
#pragma unroll 2
    for (int kc = 0; kc < 16; kc++) {
        int k0 = kc * 8;
        uint32_t a[2][4];
#pragma unroll
        for (int mi = 0; mi < 2; mi++) {
            int row = 32 * wm + 16 * mi + tg8;
            a[mi][0] = sA[row * ASTR + k0 + tq];
            a[mi][1] = sA[(row + 8) * ASTR + k0 + tq];
            a[mi][2] = sA[row * ASTR + k0 + tq + 4];
            a[mi][3] = sA[(row + 8) * ASTR + k0 + tq + 4];
        }
#pragma unroll
        for (int ni = 0; ni < 8; ni++) {
            int col = 64 * wn + 8 * ni + tg8;
            uint32_t b0 = sB[(k0 + tq) * ASTR + col];
            uint32_t b1r = sB[(k0 + tq + 4) * ASTR + col];
            mma_tf32(c[0][ni], a[0], b0, b1r);
            mma_tf32(c[1][ni], a[1], b0, b1r);
        }
    }
    __syncthreads();

    cudaGridDependencySynchronize();   // wait for k_agg (g_agg complete)

    // ---- load pass 1 tiles: A = agg rows, B = Wneigh ----
    for (int it = tid; it < 128 * 32; it += 256) {
        int r = it >> 5, q = it & 31;
        float4 vm = make_float4(0.f, 0.f, 0.f, 0.f);
        if (r < valid)
            vm = ((const float4*)agg)[(size_t)(nb + r) * 32 + q];
        uint32_t* a = sA + r * ASTR + q * 4;
        a[0] = f2tf32(vm.x); a[1] = f2tf32(vm.y);
        a[2] = f2tf32(vm.z); a[3] = f2tf32(vm.w);
        float4 w = ((const float4*)Wneigh)[it];
        uint32_t* bp = sB + r * ASTR + q * 4;
        bp[0] = f2tf32(w.x); bp[1] = f2tf32(w.y);
        bp[2] = f2tf32(w.z); bp[3] = f2tf32(w.w);
    }
    __syncthreads();

    // ---- pass 1: C += M @ Wn ----
#pragma unroll 2
    for (int kc = 0; kc < 16; kc++) {
        int k0 = kc * 8;
        uint32_t a[2][4];
#pragma unroll
        for (int mi = 0; mi < 2; mi++) {
            int row = 32 * wm + 16 * mi + tg8;
            a[mi][0] = sA[row * ASTR + k0 + tq];
            a[mi][1] = sA[(row + 8) * ASTR + k0 + tq];
            a[mi][2] = sA[row * ASTR + k0 + tq + 4];
            a[mi][3] = sA[(row + 8) * ASTR + k0 + tq + 4];
        }
#pragma unroll
        for (int ni = 0; ni < 8; ni++) {
            int col = 64 * wn + 8 * ni + tg8;
            uint32_t b0 = sB[(k0 + tq) * ASTR + col];
            uint32_t b1r = sB[(k0 + tq + 4) * ASTR + col];
            mma_tf32(c[0][ni], a[0], b0, b1r);
            mma_tf32(c[1][ni], a[1], b0, b1r);
        }
    }

    __syncthreads();
    float* sH = (float*)sA;
#pragma unroll
    for (int mi = 0; mi < 2; mi++) {
        int r0 = 32 * wm + 16 * mi + tg8;
#pragma unroll
        for (int ni = 0; ni < 8; ni++) {
            int cb = 64 * wn + 8 * ni + 2 * tq;
            sH[r0 * ASTR + cb] = fmaxf(c[mi][ni][0] + sBias[cb], 0.f);
            sH[r0 * ASTR + cb + 1] = fmaxf(c[mi][ni][1] + sBias[cb + 1], 0.f);
            sH[(r0 + 8) * ASTR + cb] = fmaxf(c[mi][ni][2] + sBias[cb], 0.f);
            sH[(r0 + 8) * ASTR + cb + 1] =
                fmaxf(c[mi][ni][3] + sBias[cb + 1], 0.f);
        }
    }
    __syncthreads();

    int node = tid >> 1;
    int half = tid & 1;
    float pv[8] = {0, 0, 0, 0, 0, 0, 0, 0};
    const float* hrow = sH + node * ASTR + half * 64;
#pragma unroll 8
    for (int j = 0; j < 64; j++) {
        float h = hrow[j];
        int col = half * 64 + j;
        float4 w0 = *(const float4*)(sWc + col * 8);
        float4 w1 = *(const float4*)(sWc + col * 8 + 4);
        pv[0] += h * w0.x; pv[1] += h * w0.y;
        pv[2] += h * w0.z; pv[3] += h * w0.w;
        pv[4] += h * w1.x; pv[5] += h * w1.y;
        pv[6] += h * w1.z; pv[7] += h * w1.w;
    }
#pragma unroll
    for (int m = 0; m < 8; m++)
        pv[m] += __shfl_xor_sync(0xffffffffu, pv[m], 1);
    int gn = nb + node;
    if (half == 0 && gn < N_NODES) {
        g_vself[gn] = make_float4(pv[0], pv[1], pv[4], pv[5]);
        g_vnb[gn] = make_float4(pv[2], pv[3], pv[6], pv[7]);
    }
}

// ======== kernel 4: tiny aggregation -> barrier -> edge scores ==============
__global__ void __launch_bounds__(NTHR, 1)
k_tailedge(const int* __restrict__ src, const int* __restrict__ dst,
           const float* __restrict__ bpred, float* __restrict__ out) {
    int bid = blockIdx.x;
    int tid = threadIdx.x;
    int lane = tid & 31;
    int gw = bid * 32 + (tid >> 5);
    int gid = bid * NTHR + tid;

    // preload for agg2 phase (8 lanes/node, 4 nodes/warp; single pass)
    int sub = lane & 7;
    int n = gw * 4 + (lane >> 3);          // 0..18943
    int d = 0, beg = 0;
    if (n < N_NODES) {
        d = g_cnt[n];
        beg = n * CAP;
    }
    int idx[8];
#pragma unroll
    for (int i = 0; i < 8; i++)
        idx[i] = (sub + 8 * i < d) ? g_csr[beg + sub + 8 * i] : -1;

    // preload for edge phase (one 8-edge group per thread)
    int4 es0 = make_int4(0, 0, 0, 0), es1 = es0, ed0 = es0, ed1 = es0;
    bool has_edge = gid < N_EDGES / 8;
    if (has_edge) {
        es0 = ((const int4*)src)[2 * gid];
        es1 = ((const int4*)src)[2 * gid + 1];
        ed0 = ((const int4*)dst)[2 * gid];
        ed1 = ((const int4*)dst)[2 * gid + 1];
    }
    float b0 = __ldg(bpred) + g_c[0] + g_c[2];
    float b1v = __ldg(bpred + 1) + g_c[1] + g_c[3];

    cudaGridDependencySynchronize();   // wait k_layer_mma (g_vnb/g_vself)

    // ---- agg2: gather projected neighbor terms, reduce over 8 lanes -------
    {
        float ax = 0.f, ay = 0.f, az = 0.f, aw = 0.f;
#pragma unroll
        for (int i = 0; i < 8; i++) {
            if (idx[i] >= 0) {
                float4 v = g_vnb[idx[i]];
                ax += v.x; ay += v.y; az += v.z; aw += v.w;
            }
        }
        for (int i = 64 + sub; i < d; i += 8) {   // rare tail (deg > 64)
            int s = g_csr[beg + i];
            float4 v = g_vnb[s];
            ax += v.x; ay += v.y; az += v.z; aw += v.w;
        }
#pragma unroll
        for (int off = 4; off > 0; off >>= 1) {
            ax += __shfl_xor_sync(0xffffffffu, ax, off);
            ay += __shfl_xor_sync(0xffffffffu, ay, off);
            az += __shfl_xor_sync(0xffffffffu, az, off);
            aw += __shfl_xor_sync(0xffffffffu, aw, off);
        }
        if (sub == 0 && n < N_NODES) {
            float inv = 1.0f / (float)(d < 1 ? 1 : d);
            float4 vs = g_vself[n];
            g_ps[n] = make_float2(vs.x + ax * inv, vs.y + ay * inv);
            g_pd[n] = make_float2(vs.z + az * inv, vs.w + aw * inv);
            g_cnt[n] = 0;   // restore invariant for next graph replay
        }
    }

    // ---- grid barrier (all 148 CTAs co-resident, no smem) -----------------
    __syncthreads();
    if (tid == 0) {
        __threadfence();
        unsigned a = atomicAdd(&g_bar_a, 1u) + 1u;
        if (a < NBLK) {
            while (*(volatile unsigned*)&g_bar_a < NBLK) {}
        }
        __threadfence();
        unsigned dcnt = atomicAdd(&g_bar_d, 1u) + 1u;
        if (dcnt == NBLK) {
            g_bar_a = 0u;
            __threadfence();
            g_bar_d = 0u;
        }
    }
    __syncthreads();

    // ---- edge scores -------------------------------------------------------
    if (has_edge) {
        int t = gid;
        float2 a0 = g_ps[es0.x], a1 = g_ps[es0.y];
        float2 a2 = g_ps[es0.z], a3 = g_ps[es0.w];
        float2 a4 = g_ps[es1.x], a5 = g_ps[es1.y];
        float2 a6 = g_ps[es1.z], a7 = g_ps[es1.w];
        float2 c0 = g_pd[ed0.x], c1 = g_pd[ed0.y];
        float2 c2 = g_pd[ed0.z], c3 = g_pd[ed0.w];
        float2 c4 = g_pd[ed1.x], c5 = g_pd[ed1.y];
        float2 c6 = g_pd[ed1.z], c7 = g_pd[ed1.w];
        float4 o;
        o = make_float4(a0.x + c0.x + b0, a0.y + c0.y + b1v,
                        a1.x + c1.x + b0, a1.y + c1.y + b1v);
        ((float4*)out)[t * 4] = o;
        o = make_float4(a2.x + c2.x + b0, a2.y + c2.y + b1v,
                        a3.x + c3.x + b0, a3.y + c3.y + b1v);
        ((float4*)out)[t * 4 + 1] = o;
        o = make_float4(a4.x + c4.x + b0, a4.y + c4.y + b1v,
                        a5.x + c5.x + b0, a5.y + c5.y + b1v);
        ((float4*)out)[t * 4 + 2] = o;
        o = make_float4(a6.x + c6.x + b0, a6.y + c6.y + b1v,
                        a7.x + c7.x + b0, a7.y + c7.y + b1v);
        ((float4*)out)[t * 4 + 3] = o;
    }
}

// ---------------- launcher (4 kernels, PDL-chained) -------------------------
static void launch_pdl(const void* func, dim3 grid, dim3 block, size_t smem,
                       void** args) {
    cudaLaunchConfig_t cfg = {};
    cfg.gridDim = grid;
    cfg.blockDim = block;
    cfg.dynamicSmemBytes = smem;
    cfg.stream = 0;
    cudaLaunchAttribute attr;
    attr.id = cudaLaunchAttributeProgrammaticStreamSerialization;
    attr.val.programmaticStreamSerializationAllowed = 1;
    cfg.attrs = &attr;
    cfg.numAttrs = 1;
    cudaLaunchKernelExC(&cfg, func, args);
}

extern "C" void kernel_launch(void* const* d_in, const int* in_sizes, int n_in,
                              void* d_out, int out_size) {
    const float* x = (const float*)d_in[0];
    const int* src = (const int*)d_in[1];
    const int* dst = (const int*)d_in[2];
    const float* Wself1 = (const float*)d_in[3];
    const float* Wneigh1 = (const float*)d_in[4];
    const float* b1 = (const float*)d_in[5];
    const float* Wself2 = (const float*)d_in[6];
    const float* Wneigh2 = (const float*)d_in[7];
    const float* b2 = (const float*)d_in[8];
    const float* Wpred = (const float*)d_in[9];
    const float* bpred = (const float*)d_in[10];
    float* out = (float*)d_out;

    size_t layer_smem = (size_t)(2 * 128 * ASTR + 1024 + 128) * 4;
    cudaFuncSetAttribute(k_layer_mma,
                         cudaFuncAttributeMaxDynamicSharedMemorySize,
                         (int)layer_smem);

    float* p_agg;
    cudaGetSymbolAddress((void**)&p_agg, g_agg);

    const int TPB = 256;
    int warp_blocks = (N_NODES * 32 + TPB - 1) / TPB;   // 1250

    k_prep<<<FILL_BLOCKS + CVT_BLOCKS + 1, TPB>>>(src, dst, x, Wself2, Wneigh2,
                                                  b2, Wpred);
    {
        void* args[] = {(void*)&x};
        launch_pdl((const void*)k_agg, dim3(warp_blocks), dim3(TPB), 0, args);
    }
    {
        void* args[] = {(void*)&x, (void*)&p_agg, (void*)&Wself1,
                        (void*)&Wneigh1, (void*)&b1};
        launch_pdl((const void*)k_layer_mma, dim3(GEMM_BLOCKS), dim3(256),
                   layer_smem, args);
    }
    {
        void* args[] = {(void*)&src, (void*)&dst, (void*)&bpred, (void*)&out};
        launch_pdl((const void*)k_tailedge, dim3(NBLK), dim3(NTHR), 0, args);
    }
}

// round 17
// speedup vs baseline: 1.1722x; 1.1075x over previous
#include <cuda_runtime.h>
#include <cuda_bf16.h>
#include <cstdint>

#define N_NODES 10000
#define N_EDGES 640000
#define D 128
#define CAP 160            // padded CSR bucket capacity (mean deg 64, sigma 8)
#define GEMM_BLOCKS 79     // ceil(10000/128)
#define NBLK 148
#define NTHR 1024
#define NWARP (NBLK * 32)  // 4736
#define NHALF (NWARP * 2)  // 9472 half-warps

// ---------------- scratch (device globals; no allocation allowed) ----------
__device__ float g_agg[N_NODES * D];
__device__ uint2 g_xh[N_NODES * 32];  // x in packed bf16
__device__ float4 g_vself[N_NODES];   // (A1 , A3) self terms
__device__ float4 g_vnb[N_NODES];     // (A2 , A4) neighbor terms
__device__ float2 g_ps[N_NODES];
__device__ float2 g_pd[N_NODES];
__device__ float g_wc[D * 8];         // [A1|A2|A3|A4] rows
__device__ float g_c[4];
__device__ int g_cnt[N_NODES];        // zeroed in k_tailedge (replay invariant)
__device__ int g_csr[N_NODES * CAP];
__device__ unsigned g_bar_a[2];       // self-resetting barriers
__device__ unsigned g_bar_d[2];

// ---------------- helpers ---------------------------------------------------
__device__ __forceinline__ uint32_t f2tf32(float v) {
    uint32_t t;
    asm("cvt.rna.tf32.f32 %0, %1;" : "=r"(t) : "f"(v));
    return t;
}
__device__ __forceinline__ void mma_tf32(float* c, const uint32_t* a,
                                         uint32_t b0, uint32_t b1) {
    asm volatile(
        "mma.sync.aligned.m16n8k8.row.col.f32.tf32.tf32.f32 "
        "{%0,%1,%2,%3}, {%4,%5,%6,%7}, {%8,%9}, {%0,%1,%2,%3};"
        : "+f"(c[0]), "+f"(c[1]), "+f"(c[2]), "+f"(c[3])
        : "r"(a[0]), "r"(a[1]), "r"(a[2]), "r"(a[3]), "r"(b0), "r"(b1));
}

// grid barrier: all NBLK CTAs co-resident (148 blocks, 1 per SM, wave 1)
__device__ __forceinline__ void grid_sync(int i) {
    __syncthreads();
    if (threadIdx.x == 0) {
        __threadfence();
        unsigned a = atomicAdd(&g_bar_a[i], 1u) + 1u;
        if (a < NBLK) {
            while (*(volatile unsigned*)&g_bar_a[i] < NBLK) {}
        }
        __threadfence();
        unsigned dcnt = atomicAdd(&g_bar_d[i], 1u) + 1u;
        if (dcnt == NBLK) {
            g_bar_a[i] = 0u;
            __threadfence();
            g_bar_d[i] = 0u;
        }
    }
    __syncthreads();
}

// accumulate a uint4 of 8 packed bf16 into 8 fp32 accumulators
__device__ __forceinline__ void acc_u4(uint4 u, float* a) {
    float2 f;
    f = __bfloat1622float2(*reinterpret_cast<__nv_bfloat162*>(&u.x));
    a[0] += f.x; a[1] += f.y;
    f = __bfloat1622float2(*reinterpret_cast<__nv_bfloat162*>(&u.y));
    a[2] += f.x; a[3] += f.y;
    f = __bfloat1622float2(*reinterpret_cast<__nv_bfloat162*>(&u.z));
    a[4] += f.x; a[5] += f.y;
    f = __bfloat1622float2(*reinterpret_cast<__nv_bfloat162*>(&u.w));
    a[6] += f.x; a[7] += f.y;
}

// ======== kernel 1: prep (fill + cvt + wc) -> barrier -> half-warp agg =====
__global__ void __launch_bounds__(NTHR, 1)
k_prepagg(const int* __restrict__ src, const int* __restrict__ dst,
          const float* __restrict__ x,
          const float* __restrict__ Ws2, const float* __restrict__ Wn2,
          const float* __restrict__ b2, const float* __restrict__ Wp) {
    __shared__ float sWp[256 * 2];
    int bid = blockIdx.x;
    int tid = threadIdx.x;
    int widx = tid >> 5;
    int lane = tid & 31;
    int gw = bid * 32 + widx;

    // ---- phase A: CSR fill + bf16 cvt (blocks 0-146) | weight fold (147) --
    if (bid < NBLK - 1) {
        int tg = bid * NTHR + tid;
        const int NT0 = (NBLK - 1) * NTHR;   // 150528
        for (int t = tg; t < N_EDGES / 8; t += NT0) {
            int4 s0 = ((const int4*)src)[2 * t];
            int4 s1 = ((const int4*)src)[2 * t + 1];
            int4 d0 = ((const int4*)dst)[2 * t];
            int4 d1 = ((const int4*)dst)[2 * t + 1];
            int p0 = atomicAdd(&g_cnt[d0.x], 1);
            int p1 = atomicAdd(&g_cnt[d0.y], 1);
            int p2 = atomicAdd(&g_cnt[d0.z], 1);
            int p3 = atomicAdd(&g_cnt[d0.w], 1);
            int p4 = atomicAdd(&g_cnt[d1.x], 1);
            int p5 = atomicAdd(&g_cnt[d1.y], 1);
            int p6 = atomicAdd(&g_cnt[d1.z], 1);
            int p7 = atomicAdd(&g_cnt[d1.w], 1);
            if (p0 < CAP) g_csr[d0.x * CAP + p0] = s0.x;
            if (p1 < CAP) g_csr[d0.y * CAP + p1] = s0.y;
            if (p2 < CAP) g_csr[d0.z * CAP + p2] = s0.z;
            if (p3 < CAP) g_csr[d0.w * CAP + p3] = s0.w;
            if (p4 < CAP) g_csr[d1.x * CAP + p4] = s1.x;
            if (p5 < CAP) g_csr[d1.y * CAP + p5] = s1.y;
            if (p6 < CAP) g_csr[d1.z * CAP + p6] = s1.z;
            if (p7 < CAP) g_csr[d1.w * CAP + p7] = s1.w;
        }
        for (int i = tg; i < N_NODES * 16; i += NT0) {
            float4 a = ((const float4*)x)[2 * i];
            float4 b = ((const float4*)x)[2 * i + 1];
            __nv_bfloat162 q0 = __floats2bfloat162_rn(a.x, a.y);
            __nv_bfloat162 q1 = __floats2bfloat162_rn(a.z, a.w);
            __nv_bfloat162 q2 = __floats2bfloat162_rn(b.x, b.y);
            __nv_bfloat162 q3 = __floats2bfloat162_rn(b.z, b.w);
            uint4 u;
            u.x = *reinterpret_cast<unsigned*>(&q0);
            u.y = *reinterpret_cast<unsigned*>(&q1);
            u.z = *reinterpret_cast<unsigned*>(&q2);
            u.w = *reinterpret_cast<unsigned*>(&q3);
            ((uint4*)g_xh)[i] = u;
        }
    } else {
        for (int i = tid; i < 512; i += NTHR) sWp[i] = Wp[i];
        __syncthreads();
        if (tid < 128) {
            int t = tid;
            float a[8] = {0, 0, 0, 0, 0, 0, 0, 0};
#pragma unroll 4
            for (int j = 0; j < D; j++) {
                float ws = Ws2[t * D + j];
                float wn = Wn2[t * D + j];
                float p0 = sWp[j * 2], p1 = sWp[j * 2 + 1];
                float q0 = sWp[(128 + j) * 2], q1 = sWp[(128 + j) * 2 + 1];
                a[0] += ws * p0; a[1] += ws * p1;
                a[2] += wn * p0; a[3] += wn * p1;
                a[4] += ws * q0; a[5] += ws * q1;
                a[6] += wn * q0; a[7] += wn * q1;
            }
#pragma unroll
            for (int j = 0; j < 8; j++) g_wc[t * 8 + j] = a[j];
        }
        if (tid < 4) {
            int half = tid >> 1, c = tid & 1;
            float s = 0.f;
            for (int j = 0; j < D; j++)
                s += b2[j] * sWp[(half * 128 + j) * 2 + c];
            g_c[tid] = s;
        }
    }
    grid_sync(0);
    cudaTriggerProgrammaticLaunchCompletion();  // release k_layer_mma

    // ---- phase B: HALF-WARP per node aggregation --------------------------
    // 9472 half-warps over 10000 nodes (~1.06 each). Lane (0..15) owns a
    // uint4 = 16 bytes of the 256B bf16 row. Same 8-index broadcast rounds.
    {
        int hl = lane & 15;                    // lane within half-warp
        unsigned hmask = (lane < 16) ? 0xffffu : 0xffff0000u;
        int hw = gw * 2 + (lane >> 4);         // half-warp id 0..9471
        for (int n = hw; n < N_NODES; n += NHALF) {
            int beg = n * CAP;
            int d = g_cnt[n];
            float a[8] = {0, 0, 0, 0, 0, 0, 0, 0};
            for (int base = 0; base < d; base += 16) {
                int my = -1;
                if (base + hl < d) my = g_csr[beg + base + hl];
                int cnt = min(16, d - base);
                int j = 0;
                for (; j + 8 <= cnt; j += 8) {
                    int ss[8];
#pragma unroll
                    for (int q = 0; q < 8; q++)
                        ss[q] = __shfl_sync(hmask, my, j + q, 16);
                    uint4 u[8];
#pragma unroll
                    for (int q = 0; q < 8; q++)
                        u[q] = ((const uint4*)g_xh)[ss[q] * 16 + hl];
#pragma unroll
                    for (int q = 0; q < 8; q++) acc_u4(u[q], a);
                }
                for (; j < cnt; j++) {
                    int s0 = __shfl_sync(hmask, my, j, 16);
                    uint4 u0 = ((const uint4*)g_xh)[s0 * 16 + hl];
                    acc_u4(u0, a);
                }
            }
            float inv = 1.0f / (float)(d < 1 ? 1 : d);
            float4 r0, r1;
            r0.x = a[0] * inv; r0.y = a[1] * inv;
            r0.z = a[2] * inv; r0.w = a[3] * inv;
            r1.x = a[4] * inv; r1.y = a[5] * inv;
            r1.z = a[6] * inv; r1.w = a[7] * inv;
            *(float4*)(g_agg + (size_t)n * D + hl * 8) = r0;
            *(float4*)(g_agg + (size_t)n * D + hl * 8 + 4) = r1;
        }
    }
}

// ======== kernel 2: mma.sync tf32 layer 1 + fused projection ================
#define ASTR 132   // 128 + 4 pad (u32 units)

__global__ void __launch_bounds__(256, 1)
k_layer_mma(const float* __restrict__ x, const float* __restrict__ agg,
            const float* __restrict__ Wself, const float* __restrict__ Wneigh,
            const float* __restrict__ bias) {
    cudaTriggerProgrammaticLaunchCompletion();  // release k_tailedge early

    extern __shared__ uint32_t smu[];
    uint32_t* sA = smu;
    uint32_t* sB = smu + 128 * ASTR;
    float* sWc = (float*)(smu + 2 * 128 * ASTR);
    float* sBias = sWc + 1024;

    int tid = threadIdx.x;
    int wid = tid >> 5;
    int lane = tid & 31;
    int nb = blockIdx.x * 128;
    int valid = min(128, N_NODES - nb);

    // prologue: x, Wself, bias, wc — complete when the trigger fired
    for (int it = tid; it < 128 * 32; it += 256) {
        int r = it >> 5, q = it & 31;
        float4 vx = make_float4(0.f, 0.f, 0.f, 0.f);
        if (r < valid) vx = ((const float4*)x)[(size_t)(nb + r) * 32 + q];
        uint32_t* a = sA + r * ASTR + q * 4;
        a[0] = f2tf32(vx.x); a[1] = f2tf32(vx.y);
        a[2] = f2tf32(vx.z); a[3] = f2tf32(vx.w);
        float4 w = ((const float4*)Wself)[it];
        uint32_t* bp = sB + r * ASTR + q * 4;
        bp[0] = f2tf32(w.x); bp[1] = f2tf32(w.y);
        bp[2] = f2tf32(w.z); bp[3] = f2tf32(w.w);
    }
    for (int i = tid; i < D * 2; i += 256)
        ((float4*)sWc)[i] = ((const float4*)g_wc)[i];
    if (tid < 32) ((float4*)sBias)[tid] = ((const float4*)bias)[tid];
    __syncthreads();

    int wm = wid & 3, wn = wid >> 2;
    int tg8 = lane >> 2, tq = lane & 3;

    float c[2][8][4];
#pragma unroll
    for (int mi = 0; mi < 2; mi++)
#pragma unroll
        for (int ni = 0; ni < 8; ni++)
#pragma unroll
            for (int k = 0; k < 4; k++) c[mi][ni][k] = 0.f;

    // ---- pass 0: C = X @ Ws (overlaps agg phase of k_prepagg) ----
#pragma unroll 2
    for (int kc = 0; kc < 16; kc++) {
        int k0 = kc * 8;
        uint32_t a[2][4];
#pragma unroll
        for (int mi = 0; mi < 2; mi++) {
            int row = 32 * wm + 16 * mi + tg8;
            a[mi][0] = sA[row * ASTR + k0 + tq];
            a[mi][1] = sA[(row + 8) * ASTR + k0 + tq];
            a[mi][2] = sA[row * ASTR + k0 + tq + 4];
            a[mi][3] = sA[(row + 8) * ASTR + k0 + tq + 4];
        }
#pragma unroll
        for (int ni = 0; ni < 8; ni++) {
            int col = 64 * wn + 8 * ni + tg8;
            uint32_t b0 = sB[(k0 + tq) * ASTR + col];
            uint32_t b1r = sB[(k0 + tq + 4) * ASTR + col];
            mma_tf32(c[0][ni], a[0], b0, b1r);
            mma_tf32(c[1][ni], a[1], b0, b1r);
        }
    }
    __syncthreads();

    cudaGridDependencySynchronize();   // wait for k_prepagg (g_agg complete)

    // ---- load pass 1 tiles: A = agg rows, B = Wneigh ----
    for (int it = tid; it < 128 * 32; it += 256) {
        int r = it >> 5, q = it & 31;
        float4 vm = make_float4(0.f, 0.f, 0.f, 0.f);
        if (r < valid)
            vm = ((const float4*)agg)[(size_t)(nb + r) * 32 + q];
        uint32_t* a = sA + r * ASTR + q * 4;
        a[0] = f2tf32(vm.x); a[1] = f2tf32(vm.y);
        a[2] = f2tf32(vm.z); a[3] = f2tf32(vm.w);
        float4 w = ((const float4*)Wneigh)[it];
        uint32_t* bp = sB + r * ASTR + q * 4;
        bp[0] = f2tf32(w.x); bp[1] = f2tf32(w.y);
        bp[2] = f2tf32(w.z); bp[3] = f2tf32(w.w);
    }
    __syncthreads();

    // ---- pass 1: C += M @ Wn ----
#pragma unroll 2
    for (int kc = 0; kc < 16; kc++) {
        int k0 = kc * 8;
        uint32_t a[2][4];
#pragma unroll
        for (int mi = 0; mi < 2; mi++) {
            int row = 32 * wm + 16 * mi + tg8;
            a[mi][0] = sA[row * ASTR + k0 + tq];
            a[mi][1] = sA[(row + 8) * ASTR + k0 + tq];
            a[mi][2] = sA[row * ASTR + k0 + tq + 4];
            a[mi][3] = sA[(row + 8) * ASTR + k0 + tq + 4];
        }
#pragma unroll
        for (int ni = 0; ni < 8; ni++) {
            int col = 64 * wn + 8 * ni + tg8;
            uint32_t b0 = sB[(k0 + tq) * ASTR + col];
            uint32_t b1r = sB[(k0 + tq + 4) * ASTR + col];
            mma_tf32(c[0][ni], a[0], b0, b1r);
            mma_tf32(c[1][ni], a[1], b0, b1r);
        }
    }

    __syncthreads();
    float* sH = (float*)sA;
#pragma unroll
    for (int mi = 0; mi < 2; mi++) {
        int r0 = 32 * wm + 16 * mi + tg8;
#pragma unroll
        for (int ni = 0; ni < 8; ni++) {
            int cb = 64 * wn + 8 * ni + 2 * tq;
            sH[r0 * ASTR + cb] = fmaxf(c[mi][ni][0] + sBias[cb], 0.f);
            sH[r0 * ASTR + cb + 1] = fmaxf(c[mi][ni][1] + sBias[cb + 1], 0.f);
            sH[(r0 + 8) * ASTR + cb] = fmaxf(c[mi][ni][2] + sBias[cb], 0.f);
            sH[(r0 + 8) * ASTR + cb + 1] =
                fmaxf(c[mi][ni][3] + sBias[cb + 1], 0.f);
        }
    }
    __syncthreads();

    int node = tid >> 1;
    int half = tid & 1;
    float pv[8] = {0, 0, 0, 0, 0, 0, 0, 0};
    const float* hrow = sH + node * ASTR + half * 64;
#pragma unroll 8
    for (int j = 0; j < 64; j++) {
        float h = hrow[j];
        int col = half * 64 + j;
        float4 w0 = *(const float4*)(sWc + col * 8);
        float4 w1 = *(const float4*)(sWc + col * 8 + 4);
        pv[0] += h * w0.x; pv[1] += h * w0.y;
        pv[2] += h * w0.z; pv[3] += h * w0.w;
        pv[4] += h * w1.x; pv[5] += h * w1.y;
        pv[6] += h * w1.z; pv[7] += h * w1.w;
    }
#pragma unroll
    for (int m = 0; m < 8; m++)
        pv[m] += __shfl_xor_sync(0xffffffffu, pv[m], 1);
    int gn = nb + node;
    if (half == 0 && gn < N_NODES) {
        g_vself[gn] = make_float4(pv[0], pv[1], pv[4], pv[5]);
        g_vnb[gn] = make_float4(pv[2], pv[3], pv[6], pv[7]);
    }
}

// ======== kernel 3: tiny aggregation -> barrier -> edge scores ==============
__global__ void __launch_bounds__(NTHR, 1)
k_tailedge(const int* __restrict__ src, const int* __restrict__ dst,
           const float* __restrict__ bpred, float* __restrict__ out) {
    int bid = blockIdx.x;
    int tid = threadIdx.x;
    int lane = tid & 31;
    int gw = bid * 32 + (tid >> 5);
    int gid = bid * NTHR + tid;

    // preload for agg2 phase (8 lanes/node, 4 nodes/warp; single pass)
    int sub = lane & 7;
    int n = gw * 4 + (lane >> 3);          // 0..18943
    int d = 0, beg = 0;
    if (n < N_NODES) {
        d = g_cnt[n];
        beg = n * CAP;
    }
    int idx[8];
#pragma unroll
    for (int i = 0; i < 8; i++)
        idx[i] = (sub + 8 * i < d) ? g_csr[beg + sub + 8 * i] : -1;

    // preload for edge phase (one 8-edge group per thread)
    int4 es0 = make_int4(0, 0, 0, 0), es1 = es0, ed0 = es0, ed1 = es0;
    bool has_edge = gid < N_EDGES / 8;
    if (has_edge) {
        es0 = ((const int4*)src)[2 * gid];
        es1 = ((const int4*)src)[2 * gid + 1];
        ed0 = ((const int4*)dst)[2 * gid];
        ed1 = ((const int4*)dst)[2 * gid + 1];
    }
    float b0 = __ldg(bpred) + g_c[0] + g_c[2];
    float b1v = __ldg(bpred + 1) + g_c[1] + g_c[3];

    cudaGridDependencySynchronize();   // wait k_layer_mma (g_vnb/g_vself)

    // ---- agg2: gather projected neighbor terms, reduce over 8 lanes -------
    {
        float ax = 0.f, ay = 0.f, az = 0.f, aw = 0.f;
#pragma unroll
        for (int i = 0; i < 8; i++) {
            if (idx[i] >= 0) {
                float4 v = g_vnb[idx[i]];
                ax += v.x; ay += v.y; az += v.z; aw += v.w;
            }
        }
        for (int i = 64 + sub; i < d; i += 8) {   // rare tail (deg > 64)
            int s = g_csr[beg + i];
            float4 v = g_vnb[s];
            ax += v.x; ay += v.y; az += v.z; aw += v.w;
        }
#pragma unroll
        for (int off = 4; off > 0; off >>= 1) {
            ax += __shfl_xor_sync(0xffffffffu, ax, off);
            ay += __shfl_xor_sync(0xffffffffu, ay, off);
            az += __shfl_xor_sync(0xffffffffu, az, off);
            aw += __shfl_xor_sync(0xffffffffu, aw, off);
        }
        if (sub == 0 && n < N_NODES) {
            float inv = 1.0f / (float)(d < 1 ? 1 : d);
            float4 vs = g_vself[n];
            g_ps[n] = make_float2(vs.x + ax * inv, vs.y + ay * inv);
            g_pd[n] = make_float2(vs.z + az * inv, vs.w + aw * inv);
            g_cnt[n] = 0;   // restore invariant for next graph replay
        }
    }

    grid_sync(1);

    // ---- edge scores -------------------------------------------------------
    if (has_edge) {
        int t = gid;
        float2 a0 = g_ps[es0.x], a1 = g_ps[es0.y];
        float2 a2 = g_ps[es0.z], a3 = g_ps[es0.w];
        float2 a4 = g_ps[es1.x], a5 = g_ps[es1.y];
        float2 a6 = g_ps[es1.z], a7 = g_ps[es1.w];
        float2 c0 = g_pd[ed0.x], c1 = g_pd[ed0.y];
        float2 c2 = g_pd[ed0.z], c3 = g_pd[ed0.w];
        float2 c4 = g_pd[ed1.x], c5 = g_pd[ed1.y];
        float2 c6 = g_pd[ed1.z], c7 = g_pd[ed1.w];
        float4 o;
        o = make_float4(a0.x + c0.x + b0, a0.y + c0.y + b1v,
                        a1.x + c1.x + b0, a1.y + c1.y + b1v);
        ((float4*)out)[t * 4] = o;
        o = make_float4(a2.x + c2.x + b0, a2.y + c2.y + b1v,
                        a3.x + c3.x + b0, a3.y + c3.y + b1v);
        ((float4*)out)[t * 4 + 1] = o;
        o = make_float4(a4.x + c4.x + b0, a4.y + c4.y + b1v,
                        a5.x + c5.x + b0, a5.y + c5.y + b1v);
        ((float4*)out)[t * 4 + 2] = o;
        o = make_float4(a6.x + c6.x + b0, a6.y + c6.y + b1v,
                        a7.x + c7.x + b0, a7.y + c7.y + b1v);
        ((float4*)out)[t * 4 + 3] = o;
    }
}

// ---------------- launcher (3 kernels, PDL-chained) -------------------------
static void launch_pdl(const void* func, dim3 grid, dim3 block, size_t smem,
                       void** args) {
    cudaLaunchConfig_t cfg = {};
    cfg.gridDim = grid;
    cfg.blockDim = block;
    cfg.dynamicSmemBytes = smem;
    cfg.stream = 0;
    cudaLaunchAttribute attr;
    attr.id = cudaLaunchAttributeProgrammaticStreamSerialization;
    attr.val.programmaticStreamSerializationAllowed = 1;
    cfg.attrs = &attr;
    cfg.numAttrs = 1;
    cudaLaunchKernelExC(&cfg, func, args);
}

extern "C" void kernel_launch(void* const* d_in, const int* in_sizes, int n_in,
                              void* d_out, int out_size) {
    const float* x = (const float*)d_in[0];
    const int* src = (const int*)d_in[1];
    const int* dst = (const int*)d_in[2];
    const float* Wself1 = (const float*)d_in[3];
    const float* Wneigh1 = (const float*)d_in[4];
    const float* b1 = (const float*)d_in[5];
    const float* Wself2 = (const float*)d_in[6];
    const float* Wneigh2 = (const float*)d_in[7];
    const float* b2 = (const float*)d_in[8];
    const float* Wpred = (const float*)d_in[9];
    const float* bpred = (const float*)d_in[10];
    float* out = (float*)d_out;

    size_t layer_smem = (size_t)(2 * 128 * ASTR + 1024 + 128) * 4;
    cudaFuncSetAttribute(k_layer_mma,
                         cudaFuncAttributeMaxDynamicSharedMemorySize,
                         (int)layer_smem);

    float* p_agg;
    cudaGetSymbolAddress((void**)&p_agg, g_agg);

    k_prepagg<<<NBLK, NTHR>>>(src, dst, x, Wself2, Wneigh2, b2, Wpred);
    {
        void* args[] = {(void*)&x, (void*)&p_agg, (void*)&Wself1,
                        (void*)&Wneigh1, (void*)&b1};
        launch_pdl((const void*)k_layer_mma, dim3(GEMM_BLOCKS), dim3(256),
                   layer_smem, args);
    }
    {
        void* args[] = {(void*)&src, (void*)&dst, (void*)&bpred, (void*)&out};
        launch_pdl((const void*)k_tailedge, dim3(NBLK), dim3(NTHR), 0, args);
    }
}